// round 6
// baseline (speedup 1.0000x reference)
#include <cuda_runtime.h>
#include <cstdint>
#include <cstddef>

#define CB 2
#define CN 2048
#define CQD 1024
#define CH 16
#define CD 64
#define CI 1024
#define ATT_SCALE 0.125f

// Scratch (allocation-free rule: __device__ globals)
__device__ float g_q[(size_t)CB * CH * CN * CD];
__device__ float g_k[(size_t)CB * CH * CN * CD];
__device__ float g_v[(size_t)CB * CH * CN * CD];
__device__ float g_ao[(size_t)CB * CN * CI];

// ---------------------------------------------------------------------------
// Tiled SGEMM: C[4096 x 1024] = A[4096,1024] @ W(window), optional bias/scale.
// mode 0: row-major out[m*1024+c]; mode 1: head-split out[b][h][n][d].
// ---------------------------------------------------------------------------
__global__ __launch_bounds__(256) void gemm128(
    const float* __restrict__ A, const float* __restrict__ W,
    const float* __restrict__ bo, float* __restrict__ out,
    int ldw, int mode, float scale)
{
    __shared__ float As[16][132];   // As[k][m] (transposed A tile)
    __shared__ float Bs[16][132];   // Bs[k][n]
    const int tid = threadIdx.x;
    const int tx = tid & 15, ty = tid >> 4;
    const int bm = blockIdx.y << 7, bn = blockIdx.x << 7;

    float acc[8][8];
#pragma unroll
    for (int i = 0; i < 8; i++)
#pragma unroll
        for (int j = 0; j < 8; j++) acc[i][j] = 0.0f;

    for (int k0 = 0; k0 < 1024; k0 += 16) {
#pragma unroll
        for (int r = 0; r < 2; r++) {
            int idx = tid + (r << 8);          // 0..511 (512 float4 per tile)
            int am = idx >> 2;                 // 0..127
            int ak = (idx & 3) << 2;           // 0,4,8,12
            float4 av = *(const float4*)(A + (size_t)(bm + am) * 1024 + k0 + ak);
            As[ak + 0][am] = av.x;
            As[ak + 1][am] = av.y;
            As[ak + 2][am] = av.z;
            As[ak + 3][am] = av.w;
            int bk  = idx >> 5;                // 0..15
            int bn2 = (idx & 31) << 2;         // 0..124
            *(float4*)&Bs[bk][bn2] =
                *(const float4*)(W + (size_t)(k0 + bk) * ldw + bn + bn2);
        }
        __syncthreads();
#pragma unroll
        for (int kk = 0; kk < 16; kk++) {
            float a[8], b[8];
            *(float4*)&a[0] = *(float4*)&As[kk][(ty << 2)];
            *(float4*)&a[4] = *(float4*)&As[kk][64 + (ty << 2)];
            *(float4*)&b[0] = *(float4*)&Bs[kk][(tx << 2)];
            *(float4*)&b[4] = *(float4*)&Bs[kk][64 + (tx << 2)];
#pragma unroll
            for (int i = 0; i < 8; i++)
#pragma unroll
                for (int j = 0; j < 8; j++)
                    acc[i][j] = fmaf(a[i], b[j], acc[i][j]);
        }
        __syncthreads();
    }

#pragma unroll
    for (int i = 0; i < 8; i++) {
        int row = bm + ((i & 4) << 4) + (ty << 2) + (i & 3);
#pragma unroll
        for (int jh = 0; jh < 2; jh++) {
            int col = bn + (jh << 6) + (tx << 2);
            float4 v;
            v.x = acc[i][jh * 4 + 0] * scale;
            v.y = acc[i][jh * 4 + 1] * scale;
            v.z = acc[i][jh * 4 + 2] * scale;
            v.w = acc[i][jh * 4 + 3] * scale;
            if (bo) {
                v.x += bo[col + 0]; v.y += bo[col + 1];
                v.z += bo[col + 2]; v.w += bo[col + 3];
            }
            if (mode == 0) {
                *(float4*)(out + (size_t)row * 1024 + col) = v;
            } else {
                int b_ = row >> 11, n_ = row & 2047;
                int h_ = col >> 6,  d_ = col & 63;
                *(float4*)(out + ((((size_t)b_ * CH + h_) * CN + n_) << 6) + d_) = v;
            }
        }
    }
}

// ---------------------------------------------------------------------------
// Flash attention: one block = (64 q-rows, one head, one batch); loops 32 key
// tiles of 64. Online softmax, bias add, key mask, O accumulated in regs.
// ---------------------------------------------------------------------------
__global__ __launch_bounds__(256) void attn_kernel(
    const float* __restrict__ bias, const int* __restrict__ mask,
    const float* __restrict__ q, const float* __restrict__ k,
    const float* __restrict__ v, float* __restrict__ aout)
{
    extern __shared__ float sm[];
    float* Qs  = sm;                 // [64][68] Qs[d][i]   (transposed, pre-scaled)
    float* Kt  = Qs + 64 * 68;       // [64][68] Kt[d][j]   (transposed)
    float* Vs  = Kt + 64 * 68;       // [64][68] Vs[j][d]
    float* Pt  = Vs + 64 * 68;       // [64][65] Pt[j][i]   (scalar, broadcast reads)
    float* mko = Pt + 64 * 65;       // [64] additive mask

    const int tid = threadIdx.x;
    const int tx = tid & 15, ty = tid >> 4;
    const int i0 = ty << 2, j0 = tx << 2, d0 = tx << 2;
    const int qt = blockIdx.x, h = blockIdx.y, b = blockIdx.z;

    const float* qb  = q + (((size_t)b * CH + h) * CN + qt * 64) * CD;
    const float* kb0 = k + ((size_t)b * CH + h) * CN * CD;
    const float* vb0 = v + ((size_t)b * CH + h) * CN * CD;

    for (int t = tid; t < 1024; t += 256) {
        int r = t >> 4, cq = (t & 15) << 2;
        float4 av = *(const float4*)(qb + r * CD + cq);
        Qs[(cq + 0) * 68 + r] = av.x;
        Qs[(cq + 1) * 68 + r] = av.y;
        Qs[(cq + 2) * 68 + r] = av.z;
        Qs[(cq + 3) * 68 + r] = av.w;
    }

    const float NEG = -3.0e38f;
    float m_i[4], l_i[4], O[4][4];
#pragma unroll
    for (int r = 0; r < 4; r++) {
        m_i[r] = -__int_as_float(0x7f800000);   // -inf
        l_i[r] = 0.0f;
#pragma unroll
        for (int c = 0; c < 4; c++) O[r][c] = 0.0f;
    }

    for (int jt = 0; jt < 32; jt++) {
        __syncthreads();   // prev PV done with Kt/Vs/Pt
        const float* kb = kb0 + jt * 64 * CD;
        const float* vb = vb0 + jt * 64 * CD;
        for (int t = tid; t < 1024; t += 256) {
            int r = t >> 4, cq = (t & 15) << 2;
            float4 av = *(const float4*)(kb + r * CD + cq);
            Kt[(cq + 0) * 68 + r] = av.x;
            Kt[(cq + 1) * 68 + r] = av.y;
            Kt[(cq + 2) * 68 + r] = av.z;
            Kt[(cq + 3) * 68 + r] = av.w;
            float4 vv = *(const float4*)(vb + r * CD + cq);
            *(float4*)&Vs[r * 68 + cq] = vv;
        }
        if (tid < 64)
            mko[tid] = mask[b * CN + jt * 64 + tid] ? 0.0f : NEG;
        __syncthreads();

        // S = (scaled q) . k^T
        float S[4][4];
#pragma unroll
        for (int r = 0; r < 4; r++)
#pragma unroll
            for (int c = 0; c < 4; c++) S[r][c] = 0.0f;

#pragma unroll 8
        for (int kk = 0; kk < 64; kk++) {
            float4 qa  = *(float4*)&Qs[kk * 68 + i0];
            float4 ka  = *(float4*)&Kt[kk * 68 + j0];
            float ar[4] = {qa.x, qa.y, qa.z, qa.w};
            float br[4] = {ka.x, ka.y, ka.z, ka.w};
#pragma unroll
            for (int r = 0; r < 4; r++)
#pragma unroll
                for (int c = 0; c < 4; c++)
                    S[r][c] = fmaf(ar[r], br[c], S[r][c]);
        }

        const int ig = qt * 64 + i0;
        const int jg = jt * 64 + j0;
        float mk0 = mko[j0 + 0], mk1 = mko[j0 + 1], mk2 = mko[j0 + 2], mk3 = mko[j0 + 3];
#pragma unroll
        for (int r = 0; r < 4; r++) {
            float4 bv = *(const float4*)(bias + ((size_t)b * CN + ig + r) * CN + jg);
            S[r][0] += bv.x + mk0;
            S[r][1] += bv.y + mk1;
            S[r][2] += bv.z + mk2;
            S[r][3] += bv.w + mk3;
        }

        // online softmax per row (row group = 16 lanes within a half-warp)
#pragma unroll
        for (int r = 0; r < 4; r++) {
            float rmax = fmaxf(fmaxf(S[r][0], S[r][1]), fmaxf(S[r][2], S[r][3]));
#pragma unroll
            for (int sfl = 8; sfl > 0; sfl >>= 1)
                rmax = fmaxf(rmax, __shfl_xor_sync(0xffffffffu, rmax, sfl));
            float mnew  = fmaxf(m_i[r], rmax);
            float alpha = __expf(m_i[r] - mnew);
            float rs = 0.0f;
#pragma unroll
            for (int c = 0; c < 4; c++) {
                S[r][c] = __expf(S[r][c] - mnew);
                rs += S[r][c];
            }
#pragma unroll
            for (int sfl = 8; sfl > 0; sfl >>= 1)
                rs += __shfl_xor_sync(0xffffffffu, rs, sfl);
            l_i[r] = l_i[r] * alpha + rs;
            m_i[r] = mnew;
#pragma unroll
            for (int c = 0; c < 4; c++) {
                O[r][c] *= alpha;
                Pt[(j0 + c) * 65 + i0 + r] = S[r][c];
            }
        }
        __syncthreads();

        // O += P @ V
#pragma unroll 8
        for (int j = 0; j < 64; j++) {
            float4 vv = *(float4*)&Vs[j * 68 + d0];
            float va[4] = {vv.x, vv.y, vv.z, vv.w};
#pragma unroll
            for (int r = 0; r < 4; r++) {
                float p = Pt[j * 65 + i0 + r];
#pragma unroll
                for (int c = 0; c < 4; c++)
                    O[r][c] = fmaf(p, va[c], O[r][c]);
            }
        }
    }

    const int ig = qt * 64 + i0;
#pragma unroll
    for (int r = 0; r < 4; r++) {
        float inv = 1.0f / l_i[r];
        float4 o4 = make_float4(O[r][0] * inv, O[r][1] * inv,
                                O[r][2] * inv, O[r][3] * inv);
        *(float4*)(aout + ((size_t)b * CN + ig + r) * CI + h * 64 + d0) = o4;
    }
}

// ---------------------------------------------------------------------------
extern "C" void kernel_launch(void* const* d_in, const int* in_sizes, int n_in,
                              void* d_out, int out_size) {
    (void)in_sizes; (void)n_in; (void)out_size;
    const float* x    = (const float*)d_in[0];
    const float* bias = (const float*)d_in[1];
    const int*   mask = (const int*)d_in[2];
    const float* Wq   = (const float*)d_in[3];
    const float* Wkv  = (const float*)d_in[4];
    const float* Wo   = (const float*)d_in[5];
    const float* bo   = (const float*)d_in[6];
    float* out = (float*)d_out;

    float *qp, *kp, *vp, *aop;
    cudaGetSymbolAddress((void**)&qp, g_q);
    cudaGetSymbolAddress((void**)&kp, g_k);
    cudaGetSymbolAddress((void**)&vp, g_v);
    cudaGetSymbolAddress((void**)&aop, g_ao);

    const int smem_attn = (3 * 64 * 68 + 64 * 65 + 64) * 4;   // 69120 B
    cudaFuncSetAttribute(attn_kernel,
                         cudaFuncAttributeMaxDynamicSharedMemorySize, smem_attn);

    dim3 gg(8, 32), bb(256);
    // q = (x @ Wq) * scale        -> head-split layout
    gemm128<<<gg, bb>>>(x, Wq, nullptr, qp, 1024, 1, ATT_SCALE);
    // k = x @ Wkv[:, :1024]
    gemm128<<<gg, bb>>>(x, Wkv, nullptr, kp, 2048, 1, 1.0f);
    // v = x @ Wkv[:, 1024:]
    gemm128<<<gg, bb>>>(x, Wkv + 1024, nullptr, vp, 2048, 1, 1.0f);
    // fused attention (bias + key mask + softmax + PV)
    attn_kernel<<<dim3(32, 16, 2), bb, smem_attn>>>(bias, mask, qp, kp, vp, aop);
    // out = attn_out @ Wo + bo
    gemm128<<<gg, bb>>>(aop, Wo, bo, out, 1024, 0, 1.0f);
}

// round 9
// speedup vs baseline: 1.3710x; 1.3710x over previous
#include <cuda_runtime.h>
#include <cstdint>
#include <cstddef>

#define CB 2
#define CN 2048
#define CQD 1024
#define CH 16
#define CD 64
#define CI 1024
#define ATT_SCALE 0.125f

// Scratch (allocation-free rule: __device__ globals)
__device__ float g_q[(size_t)CB * CH * CN * CD];
__device__ float g_k[(size_t)CB * CH * CN * CD];
__device__ float g_v[(size_t)CB * CH * CN * CD];
__device__ float g_ao[(size_t)CB * CN * CI];

__device__ __forceinline__ uint32_t f2tf(float f) {
    uint32_t u;
    asm("cvt.rna.tf32.f32 %0, %1;" : "=r"(u) : "f"(f));
    return u;
}

__device__ __forceinline__ void mma_tf32(float* d, const uint32_t* a,
                                         const uint32_t* b) {
    asm volatile(
        "mma.sync.aligned.m16n8k8.row.col.f32.tf32.tf32.f32 "
        "{%0,%1,%2,%3},{%4,%5,%6,%7},{%8,%9},{%0,%1,%2,%3};"
        : "+f"(d[0]), "+f"(d[1]), "+f"(d[2]), "+f"(d[3])
        : "r"(a[0]), "r"(a[1]), "r"(a[2]), "r"(a[3]), "r"(b[0]), "r"(b[1]));
}

// ---------------------------------------------------------------------------
// tf32 tensor-core GEMM: C[4096 x 1024] = A[4096,1024] @ W(window).
// 128x128 block tile, K-step 32. 8 warps, each 64x32 (4x4 m16n8k8).
// mode 0: row-major out; mode 1: head-split out[b][h][n][d].
// ---------------------------------------------------------------------------
__global__ __launch_bounds__(256) void gemm_tf32(
    const float* __restrict__ A, const float* __restrict__ W,
    const float* __restrict__ bo, float* __restrict__ out,
    int ldw, int mode, float scale)
{
    __shared__ uint32_t As[128 * 36];   // [m][k], stride 36 (conflict-free frags)
    __shared__ uint32_t Bs[32 * 136];   // [k][n], stride 136

    const int tid  = threadIdx.x;
    const int lane = tid & 31, warp = tid >> 5;
    const int gid = lane >> 2, tig = lane & 3;
    const int wm = warp >> 2, wn = warp & 3;     // 2 x 4 warp grid
    const int bm = blockIdx.y << 7, bn = blockIdx.x << 7;

    float acc[4][4][4];
#pragma unroll
    for (int i = 0; i < 4; i++)
#pragma unroll
        for (int j = 0; j < 4; j++)
#pragma unroll
            for (int r = 0; r < 4; r++) acc[i][j][r] = 0.0f;

    for (int k0 = 0; k0 < 1024; k0 += 32) {
#pragma unroll
        for (int t0 = 0; t0 < 4; t0++) {
            int t = tid + (t0 << 8);
            int r = t >> 3, kc = (t & 7) << 2;
            float4 av = *(const float4*)(A + (size_t)(bm + r) * 1024 + k0 + kc);
            uint4 u = make_uint4(f2tf(av.x), f2tf(av.y), f2tf(av.z), f2tf(av.w));
            *(uint4*)&As[r * 36 + kc] = u;
            int kr = t >> 5, nc = (t & 31) << 2;
            float4 wv = *(const float4*)(W + (size_t)(k0 + kr) * ldw + bn + nc);
            uint4 w = make_uint4(f2tf(wv.x), f2tf(wv.y), f2tf(wv.z), f2tf(wv.w));
            *(uint4*)&Bs[kr * 136 + nc] = w;
        }
        __syncthreads();

#pragma unroll
        for (int q = 0; q < 4; q++) {
            const int kq = q << 3;
            uint32_t a[4][4], b[4][2];
#pragma unroll
            for (int sm = 0; sm < 4; sm++) {
                int row = (wm << 6) + (sm << 4) + gid;
                a[sm][0] = As[row * 36 + kq + tig];
                a[sm][1] = As[(row + 8) * 36 + kq + tig];
                a[sm][2] = As[row * 36 + kq + tig + 4];
                a[sm][3] = As[(row + 8) * 36 + kq + tig + 4];
            }
#pragma unroll
            for (int sn = 0; sn < 4; sn++) {
                int col = (wn << 5) + (sn << 3) + gid;
                b[sn][0] = Bs[(kq + tig) * 136 + col];
                b[sn][1] = Bs[(kq + tig + 4) * 136 + col];
            }
#pragma unroll
            for (int sm = 0; sm < 4; sm++)
#pragma unroll
                for (int sn = 0; sn < 4; sn++)
                    mma_tf32(acc[sm][sn], a[sm], b[sn]);
        }
        __syncthreads();
    }

    // Epilogue: fragment (groupID rows, tig*2 col pairs)
#pragma unroll
    for (int sm = 0; sm < 4; sm++) {
#pragma unroll
        for (int sn = 0; sn < 4; sn++) {
            int col = bn + (wn << 5) + (sn << 3) + (tig << 1);
            float bx = 0.0f, by = 0.0f;
            if (bo) { bx = bo[col]; by = bo[col + 1]; }
#pragma unroll
            for (int half = 0; half < 2; half++) {
                int row = bm + (wm << 6) + (sm << 4) + gid + (half << 3);
                float2 v;
                v.x = acc[sm][sn][half * 2 + 0] * scale + bx;
                v.y = acc[sm][sn][half * 2 + 1] * scale + by;
                if (mode == 0) {
                    *(float2*)(out + (size_t)row * 1024 + col) = v;
                } else {
                    int b_ = row >> 11, n_ = row & 2047;
                    int h_ = col >> 6,  d_ = col & 63;
                    *(float2*)(out + ((((size_t)b_ * CH + h_) * CN + n_) << 6) + d_) = v;
                }
            }
        }
    }
}

// ---------------------------------------------------------------------------
// Flash attention (unchanged from passing R6): one block = 64 q-rows, 1 head.
// ---------------------------------------------------------------------------
__global__ __launch_bounds__(256) void attn_kernel(
    const float* __restrict__ bias, const int* __restrict__ mask,
    const float* __restrict__ q, const float* __restrict__ k,
    const float* __restrict__ v, float* __restrict__ aout)
{
    extern __shared__ float sm[];
    float* Qs  = sm;                 // [64][68] Qs[d][i]
    float* Kt  = Qs + 64 * 68;       // [64][68] Kt[d][j]
    float* Vs  = Kt + 64 * 68;       // [64][68] Vs[j][d]
    float* Pt  = Vs + 64 * 68;       // [64][65] Pt[j][i]
    float* mko = Pt + 64 * 65;       // [64]

    const int tid = threadIdx.x;
    const int tx = tid & 15, ty = tid >> 4;
    const int i0 = ty << 2, j0 = tx << 2, d0 = tx << 2;
    const int qt = blockIdx.x, h = blockIdx.y, b = blockIdx.z;

    const float* qb  = q + (((size_t)b * CH + h) * CN + qt * 64) * CD;
    const float* kb0 = k + ((size_t)b * CH + h) * CN * CD;
    const float* vb0 = v + ((size_t)b * CH + h) * CN * CD;

    for (int t = tid; t < 1024; t += 256) {
        int r = t >> 4, cq = (t & 15) << 2;
        float4 av = *(const float4*)(qb + r * CD + cq);
        Qs[(cq + 0) * 68 + r] = av.x;
        Qs[(cq + 1) * 68 + r] = av.y;
        Qs[(cq + 2) * 68 + r] = av.z;
        Qs[(cq + 3) * 68 + r] = av.w;
    }

    const float NEG = -3.0e38f;
    float m_i[4], l_i[4], O[4][4];
#pragma unroll
    for (int r = 0; r < 4; r++) {
        m_i[r] = -__int_as_float(0x7f800000);
        l_i[r] = 0.0f;
#pragma unroll
        for (int c = 0; c < 4; c++) O[r][c] = 0.0f;
    }

    for (int jt = 0; jt < 32; jt++) {
        __syncthreads();
        const float* kb = kb0 + jt * 64 * CD;
        const float* vb = vb0 + jt * 64 * CD;
        for (int t = tid; t < 1024; t += 256) {
            int r = t >> 4, cq = (t & 15) << 2;
            float4 av = *(const float4*)(kb + r * CD + cq);
            Kt[(cq + 0) * 68 + r] = av.x;
            Kt[(cq + 1) * 68 + r] = av.y;
            Kt[(cq + 2) * 68 + r] = av.z;
            Kt[(cq + 3) * 68 + r] = av.w;
            float4 vv = *(const float4*)(vb + r * CD + cq);
            *(float4*)&Vs[r * 68 + cq] = vv;
        }
        if (tid < 64)
            mko[tid] = mask[b * CN + jt * 64 + tid] ? 0.0f : NEG;
        __syncthreads();

        float S[4][4];
#pragma unroll
        for (int r = 0; r < 4; r++)
#pragma unroll
            for (int c = 0; c < 4; c++) S[r][c] = 0.0f;

#pragma unroll 8
        for (int kk = 0; kk < 64; kk++) {
            float4 qa  = *(float4*)&Qs[kk * 68 + i0];
            float4 ka  = *(float4*)&Kt[kk * 68 + j0];
            float ar[4] = {qa.x, qa.y, qa.z, qa.w};
            float br[4] = {ka.x, ka.y, ka.z, ka.w};
#pragma unroll
            for (int r = 0; r < 4; r++)
#pragma unroll
                for (int c = 0; c < 4; c++)
                    S[r][c] = fmaf(ar[r], br[c], S[r][c]);
        }

        const int ig = qt * 64 + i0;
        const int jg = jt * 64 + j0;
        float mk0 = mko[j0 + 0], mk1 = mko[j0 + 1], mk2 = mko[j0 + 2], mk3 = mko[j0 + 3];
#pragma unroll
        for (int r = 0; r < 4; r++) {
            float4 bv = *(const float4*)(bias + ((size_t)b * CN + ig + r) * CN + jg);
            S[r][0] += bv.x + mk0;
            S[r][1] += bv.y + mk1;
            S[r][2] += bv.z + mk2;
            S[r][3] += bv.w + mk3;
        }

#pragma unroll
        for (int r = 0; r < 4; r++) {
            float rmax = fmaxf(fmaxf(S[r][0], S[r][1]), fmaxf(S[r][2], S[r][3]));
#pragma unroll
            for (int sfl = 8; sfl > 0; sfl >>= 1)
                rmax = fmaxf(rmax, __shfl_xor_sync(0xffffffffu, rmax, sfl));
            float mnew  = fmaxf(m_i[r], rmax);
            float alpha = __expf(m_i[r] - mnew);
            float rs = 0.0f;
#pragma unroll
            for (int c = 0; c < 4; c++) {
                S[r][c] = __expf(S[r][c] - mnew);
                rs += S[r][c];
            }
#pragma unroll
            for (int sfl = 8; sfl > 0; sfl >>= 1)
                rs += __shfl_xor_sync(0xffffffffu, rs, sfl);
            l_i[r] = l_i[r] * alpha + rs;
            m_i[r] = mnew;
#pragma unroll
            for (int c = 0; c < 4; c++) {
                O[r][c] *= alpha;
                Pt[(j0 + c) * 65 + i0 + r] = S[r][c];
            }
        }
        __syncthreads();

#pragma unroll 8
        for (int j = 0; j < 64; j++) {
            float4 vv = *(float4*)&Vs[j * 68 + d0];
            float va[4] = {vv.x, vv.y, vv.z, vv.w};
#pragma unroll
            for (int r = 0; r < 4; r++) {
                float p = Pt[j * 65 + i0 + r];
#pragma unroll
                for (int c = 0; c < 4; c++)
                    O[r][c] = fmaf(p, va[c], O[r][c]);
            }
        }
    }

    const int ig = qt * 64 + i0;
#pragma unroll
    for (int r = 0; r < 4; r++) {
        float inv = 1.0f / l_i[r];
        float4 o4 = make_float4(O[r][0] * inv, O[r][1] * inv,
                                O[r][2] * inv, O[r][3] * inv);
        *(float4*)(aout + ((size_t)b * CN + ig + r) * CI + h * 64 + d0) = o4;
    }
}

// ---------------------------------------------------------------------------
extern "C" void kernel_launch(void* const* d_in, const int* in_sizes, int n_in,
                              void* d_out, int out_size) {
    (void)in_sizes; (void)n_in; (void)out_size;
    const float* x    = (const float*)d_in[0];
    const float* bias = (const float*)d_in[1];
    const int*   mask = (const int*)d_in[2];
    const float* Wq   = (const float*)d_in[3];
    const float* Wkv  = (const float*)d_in[4];
    const float* Wo   = (const float*)d_in[5];
    const float* bo   = (const float*)d_in[6];
    float* out = (float*)d_out;

    float *qp, *kp, *vp, *aop;
    cudaGetSymbolAddress((void**)&qp, g_q);
    cudaGetSymbolAddress((void**)&kp, g_k);
    cudaGetSymbolAddress((void**)&vp, g_v);
    cudaGetSymbolAddress((void**)&aop, g_ao);

    const int smem_attn = (3 * 64 * 68 + 64 * 65 + 64) * 4;   // 69120 B
    cudaFuncSetAttribute(attn_kernel,
                         cudaFuncAttributeMaxDynamicSharedMemorySize, smem_attn);

    dim3 gg(8, 32), bb(256);
    // q = (x @ Wq) * scale        -> head-split layout
    gemm_tf32<<<gg, bb>>>(x, Wq, nullptr, qp, 1024, 1, ATT_SCALE);
    // k = x @ Wkv[:, :1024]
    gemm_tf32<<<gg, bb>>>(x, Wkv, nullptr, kp, 2048, 1, 1.0f);
    // v = x @ Wkv[:, 1024:]
    gemm_tf32<<<gg, bb>>>(x, Wkv + 1024, nullptr, vp, 2048, 1, 1.0f);
    // fused attention (bias + key mask + softmax + PV)
    attn_kernel<<<dim3(32, 16, 2), bb, smem_attn>>>(bias, mask, qp, kp, vp, aop);
    // out = attn_out @ Wo + bo
    gemm_tf32<<<gg, bb>>>(aop, Wo, bo, out, 1024, 0, 1.0f);
}

// round 11
// speedup vs baseline: 1.5044x; 1.0973x over previous
#include <cuda_runtime.h>
#include <cstdint>
#include <cstddef>

#define CB 2
#define CN 2048
#define CH 16
#define CD 64
#define CI 1024
#define ATT_SCALE 0.125f

// Scratch (allocation-free rule: __device__ globals)
__device__ float g_q[(size_t)CB * CH * CN * CD];
__device__ float g_k[(size_t)CB * CH * CN * CD];
__device__ float g_v[(size_t)CB * CH * CN * CD];
__device__ float g_ao[(size_t)CB * CN * CI];

__device__ __forceinline__ uint32_t f2tf(float f) {
    uint32_t u;
    asm("cvt.rna.tf32.f32 %0, %1;" : "=r"(u) : "f"(f));
    return u;
}

__device__ __forceinline__ void mma_tf32(float* d, const uint32_t* a,
                                         const uint32_t* b) {
    asm volatile(
        "mma.sync.aligned.m16n8k8.row.col.f32.tf32.tf32.f32 "
        "{%0,%1,%2,%3},{%4,%5,%6,%7},{%8,%9},{%0,%1,%2,%3};"
        : "+f"(d[0]), "+f"(d[1]), "+f"(d[2]), "+f"(d[3])
        : "r"(a[0]), "r"(a[1]), "r"(a[2]), "r"(a[3]), "r"(b[0]), "r"(b[1]));
}

// ---------------------------------------------------------------------------
// tf32 tensor-core GEMM (passing R9 version, unchanged).
// ---------------------------------------------------------------------------
__global__ __launch_bounds__(256) void gemm_tf32(
    const float* __restrict__ A, const float* __restrict__ W,
    const float* __restrict__ bo, float* __restrict__ out,
    int ldw, int mode, float scale)
{
    __shared__ uint32_t As[128 * 36];
    __shared__ uint32_t Bs[32 * 136];

    const int tid  = threadIdx.x;
    const int lane = tid & 31, warp = tid >> 5;
    const int gid = lane >> 2, tig = lane & 3;
    const int wm = warp >> 2, wn = warp & 3;
    const int bm = blockIdx.y << 7, bn = blockIdx.x << 7;

    float acc[4][4][4];
#pragma unroll
    for (int i = 0; i < 4; i++)
#pragma unroll
        for (int j = 0; j < 4; j++)
#pragma unroll
            for (int r = 0; r < 4; r++) acc[i][j][r] = 0.0f;

    for (int k0 = 0; k0 < 1024; k0 += 32) {
#pragma unroll
        for (int t0 = 0; t0 < 4; t0++) {
            int t = tid + (t0 << 8);
            int r = t >> 3, kc = (t & 7) << 2;
            float4 av = *(const float4*)(A + (size_t)(bm + r) * 1024 + k0 + kc);
            uint4 u = make_uint4(f2tf(av.x), f2tf(av.y), f2tf(av.z), f2tf(av.w));
            *(uint4*)&As[r * 36 + kc] = u;
            int kr = t >> 5, nc = (t & 31) << 2;
            float4 wv = *(const float4*)(W + (size_t)(k0 + kr) * ldw + bn + nc);
            uint4 w = make_uint4(f2tf(wv.x), f2tf(wv.y), f2tf(wv.z), f2tf(wv.w));
            *(uint4*)&Bs[kr * 136 + nc] = w;
        }
        __syncthreads();

#pragma unroll
        for (int q = 0; q < 4; q++) {
            const int kq = q << 3;
            uint32_t a[4][4], b[4][2];
#pragma unroll
            for (int sm = 0; sm < 4; sm++) {
                int row = (wm << 6) + (sm << 4) + gid;
                a[sm][0] = As[row * 36 + kq + tig];
                a[sm][1] = As[(row + 8) * 36 + kq + tig];
                a[sm][2] = As[row * 36 + kq + tig + 4];
                a[sm][3] = As[(row + 8) * 36 + kq + tig + 4];
            }
#pragma unroll
            for (int sn = 0; sn < 4; sn++) {
                int col = (wn << 5) + (sn << 3) + gid;
                b[sn][0] = Bs[(kq + tig) * 136 + col];
                b[sn][1] = Bs[(kq + tig + 4) * 136 + col];
            }
#pragma unroll
            for (int sm = 0; sm < 4; sm++)
#pragma unroll
                for (int sn = 0; sn < 4; sn++)
                    mma_tf32(acc[sm][sn], a[sm], b[sn]);
        }
        __syncthreads();
    }

#pragma unroll
    for (int sm = 0; sm < 4; sm++) {
#pragma unroll
        for (int sn = 0; sn < 4; sn++) {
            int col = bn + (wn << 5) + (sn << 3) + (tig << 1);
            float bx = 0.0f, by = 0.0f;
            if (bo) { bx = bo[col]; by = bo[col + 1]; }
#pragma unroll
            for (int half = 0; half < 2; half++) {
                int row = bm + (wm << 6) + (sm << 4) + gid + (half << 3);
                float2 v;
                v.x = acc[sm][sn][half * 2 + 0] * scale + bx;
                v.y = acc[sm][sn][half * 2 + 1] * scale + by;
                if (mode == 0) {
                    *(float2*)(out + (size_t)row * 1024 + col) = v;
                } else {
                    int b_ = row >> 11, n_ = row & 2047;
                    int h_ = col >> 6,  d_ = col & 63;
                    *(float2*)(out + ((((size_t)b_ * CH + h_) * CN + n_) << 6) + d_) = v;
                }
            }
        }
    }
}

// ---------------------------------------------------------------------------
// Flash attention v2: 128x128 S-tile per block, 8x8 fragment per thread.
// One block = (128 q-rows, head, batch); 16 key tiles of 128.
// Kt column-swizzled, Pt i-swizzled for bank-conflict-free access.
// ---------------------------------------------------------------------------
#define QS_STRIDE 132
#define PT_STRIDE 132
#define VS_STRIDE 68
#define SMEM_ATT ((64 * QS_STRIDE * 2 + 128 * VS_STRIDE + 128 * PT_STRIDE + 128) * 4)

__global__ __launch_bounds__(256) void attn_kernel(
    const float* __restrict__ bias, const int* __restrict__ mask,
    const float* __restrict__ q, const float* __restrict__ k,
    const float* __restrict__ v, float* __restrict__ aout)
{
    extern __shared__ float smf[];
    float* Qs  = smf;                        // [64][132]  Qs[d][i]
    float* Kt  = Qs + 64 * QS_STRIDE;        // [64][132]  Kt[d][j^swz]
    float* Vs  = Kt + 64 * QS_STRIDE;        // [128][68]  Vs[j][d]
    float* Pt  = Vs + 128 * VS_STRIDE;       // [128][132] Pt[j][i^swz]
    float* mko = Pt + 128 * PT_STRIDE;       // [128]

    const int tid = threadIdx.x;
    const int tx = tid & 15, ty = tid >> 4;
    const int i0 = ty << 3;                  // 8 rows per thread
    const int qt = blockIdx.x, h = blockIdx.y, b = blockIdx.z;

    const float* qb  = q + (((size_t)b * CH + h) * CN + qt * 128) * CD;
    const float* kb0 = k + ((size_t)b * CH + h) * CN * CD;
    const float* vb0 = v + ((size_t)b * CH + h) * CN * CD;

    // Qs fill: 128x64 -> transposed [d][i] (once)
    for (int t = tid; t < 2048; t += 256) {
        int r = t >> 4, c4 = (t & 15) << 2;
        float4 av = *(const float4*)(qb + r * CD + c4);
        Qs[(c4 + 0) * QS_STRIDE + r] = av.x;
        Qs[(c4 + 1) * QS_STRIDE + r] = av.y;
        Qs[(c4 + 2) * QS_STRIDE + r] = av.z;
        Qs[(c4 + 3) * QS_STRIDE + r] = av.w;
    }

    const float NEG = -3.0e38f;
    float m_i[8], l_i[8], O[8][4];
#pragma unroll
    for (int r = 0; r < 8; r++) {
        m_i[r] = -__int_as_float(0x7f800000);
        l_i[r] = 0.0f;
#pragma unroll
        for (int c = 0; c < 4; c++) O[r][c] = 0.0f;
    }

    for (int jt = 0; jt < 16; jt++) {
        __syncthreads();                     // prev PV done with Kt/Vs/Pt
        const float* kb = kb0 + jt * 128 * CD;
        const float* vb = vb0 + jt * 128 * CD;
        // Kt fill (transposed + column swizzle), Vs fill (row-major)
        for (int t = tid; t < 2048; t += 256) {
            int r = t >> 4, c4 = (t & 15) << 2;        // r=j, c4=d
            float4 kv = *(const float4*)(kb + r * CD + c4);
            int sw = ((c4 >> 2) & 7) << 2;             // same for c4..c4+3
            Kt[(c4 + 0) * QS_STRIDE + (r ^ sw)] = kv.x;
            Kt[(c4 + 1) * QS_STRIDE + (r ^ sw)] = kv.y;
            Kt[(c4 + 2) * QS_STRIDE + (r ^ sw)] = kv.z;
            Kt[(c4 + 3) * QS_STRIDE + (r ^ sw)] = kv.w;
            float4 vv = *(const float4*)(vb + r * CD + c4);
            *(float4*)&Vs[r * VS_STRIDE + c4] = vv;
        }
        if (tid < 128)
            mko[tid] = mask[b * CN + jt * 128 + tid] ? 0.0f : NEG;
        __syncthreads();

        // ---- S = Q.K^T (128x128 tile, 8x8 per thread) ----
        float S[8][8];
#pragma unroll
        for (int r = 0; r < 8; r++)
#pragma unroll
            for (int c = 0; c < 8; c++) S[r][c] = 0.0f;

#pragma unroll 4
        for (int kk = 0; kk < 64; kk++) {
            const float* qrow = &Qs[kk * QS_STRIDE];
            const float* krow = &Kt[kk * QS_STRIDE];
            int s = (kk >> 2) & 7;
            float4 a0 = *(const float4*)(qrow + i0);
            float4 a1 = *(const float4*)(qrow + i0 + 4);
            float4 b0 = *(const float4*)(krow + ((tx ^ s) << 2));
            float4 b1 = *(const float4*)(krow + 64 + ((tx ^ s) << 2));
            float ar[8] = {a0.x, a0.y, a0.z, a0.w, a1.x, a1.y, a1.z, a1.w};
            float br[8] = {b0.x, b0.y, b0.z, b0.w, b1.x, b1.y, b1.z, b1.w};
#pragma unroll
            for (int r = 0; r < 8; r++)
#pragma unroll
                for (int c = 0; c < 8; c++)
                    S[r][c] = fmaf(ar[r], br[c], S[r][c]);
        }

        // ---- bias + mask ----
        const int ig = qt * 128 + i0;
        const int jg = jt * 128 + (tx << 2);
        float4 mk0 = *(float4*)&mko[tx << 2];
        float4 mk1 = *(float4*)&mko[64 + (tx << 2)];
#pragma unroll
        for (int r = 0; r < 8; r++) {
            const float* brow = bias + ((size_t)b * CN + ig + r) * CN + jg;
            float4 bv0 = *(const float4*)(brow);
            float4 bv1 = *(const float4*)(brow + 64);
            S[r][0] += bv0.x + mk0.x;
            S[r][1] += bv0.y + mk0.y;
            S[r][2] += bv0.z + mk0.z;
            S[r][3] += bv0.w + mk0.w;
            S[r][4] += bv1.x + mk1.x;
            S[r][5] += bv1.y + mk1.y;
            S[r][6] += bv1.z + mk1.z;
            S[r][7] += bv1.w + mk1.w;
        }

        // ---- online softmax (row spread over 16 tx lanes) ----
#pragma unroll
        for (int r = 0; r < 8; r++) {
            float rmax = S[r][0];
#pragma unroll
            for (int c = 1; c < 8; c++) rmax = fmaxf(rmax, S[r][c]);
#pragma unroll
            for (int sfl = 8; sfl > 0; sfl >>= 1)
                rmax = fmaxf(rmax, __shfl_xor_sync(0xffffffffu, rmax, sfl));
            float mnew  = fmaxf(m_i[r], rmax);
            float alpha = __expf(m_i[r] - mnew);
            float rs = 0.0f;
#pragma unroll
            for (int c = 0; c < 8; c++) {
                S[r][c] = __expf(S[r][c] - mnew);
                rs += S[r][c];
            }
#pragma unroll
            for (int sfl = 8; sfl > 0; sfl >>= 1)
                rs += __shfl_xor_sync(0xffffffffu, rs, sfl);
            l_i[r] = l_i[r] * alpha + rs;
            m_i[r] = mnew;
#pragma unroll
            for (int c = 0; c < 4; c++) O[r][c] *= alpha;
        }

        // ---- write P^T to smem (i-swizzled) ----
        {
            int sp = tx & 7;
            int ib0 = ((ty * 2 + 0) ^ sp) << 2;
            int ib1 = ((ty * 2 + 1) ^ sp) << 2;
#pragma unroll
            for (int c = 0; c < 8; c++) {
                int j = (c < 4) ? ((tx << 2) + c) : (64 + (tx << 2) + c - 4);
                float* pr = &Pt[j * PT_STRIDE];
                *(float4*)(pr + ib0) = make_float4(S[0][c], S[1][c], S[2][c], S[3][c]);
                *(float4*)(pr + ib1) = make_float4(S[4][c], S[5][c], S[6][c], S[7][c]);
            }
        }
        __syncthreads();

        // ---- O += P @ V ----
#pragma unroll 4
        for (int j = 0; j < 128; j++) {
            int sp = (j >> 2) & 7;
            const float* pr = &Pt[j * PT_STRIDE];
            float4 pa = *(const float4*)(pr + (((ty * 2 + 0) ^ sp) << 2));
            float4 pb = *(const float4*)(pr + (((ty * 2 + 1) ^ sp) << 2));
            float4 vv = *(const float4*)&Vs[j * VS_STRIDE + (tx << 2)];
            float pv[8] = {pa.x, pa.y, pa.z, pa.w, pb.x, pb.y, pb.z, pb.w};
#pragma unroll
            for (int r = 0; r < 8; r++) {
#pragma unroll
                for (int c = 0; c < 4; c++)
                    O[r][c] = fmaf(pv[r], (&vv.x)[c], O[r][c]);
            }
        }
    }

    // ---- finalize ----
    const int ig = qt * 128 + i0;
#pragma unroll
    for (int r = 0; r < 8; r++) {
        float inv = 1.0f / l_i[r];
        float4 o4 = make_float4(O[r][0] * inv, O[r][1] * inv,
                                O[r][2] * inv, O[r][3] * inv);
        *(float4*)(aout + ((size_t)b * CN + ig + r) * CI + h * 64 + (tx << 2)) = o4;
    }
}

// ---------------------------------------------------------------------------
extern "C" void kernel_launch(void* const* d_in, const int* in_sizes, int n_in,
                              void* d_out, int out_size) {
    (void)in_sizes; (void)n_in; (void)out_size;
    const float* x    = (const float*)d_in[0];
    const float* bias = (const float*)d_in[1];
    const int*   mask = (const int*)d_in[2];
    const float* Wq   = (const float*)d_in[3];
    const float* Wkv  = (const float*)d_in[4];
    const float* Wo   = (const float*)d_in[5];
    const float* bo   = (const float*)d_in[6];
    float* out = (float*)d_out;

    float *qp, *kp, *vp, *aop;
    cudaGetSymbolAddress((void**)&qp, g_q);
    cudaGetSymbolAddress((void**)&kp, g_k);
    cudaGetSymbolAddress((void**)&vp, g_v);
    cudaGetSymbolAddress((void**)&aop, g_ao);

    cudaFuncSetAttribute(attn_kernel,
                         cudaFuncAttributeMaxDynamicSharedMemorySize, SMEM_ATT);

    dim3 gg(8, 32), bb(256);
    gemm_tf32<<<gg, bb>>>(x, Wq, nullptr, qp, 1024, 1, ATT_SCALE);
    gemm_tf32<<<gg, bb>>>(x, Wkv, nullptr, kp, 2048, 1, 1.0f);
    gemm_tf32<<<gg, bb>>>(x, Wkv + 1024, nullptr, vp, 2048, 1, 1.0f);
    attn_kernel<<<dim3(16, 16, 2), bb, SMEM_ATT>>>(bias, mask, qp, kp, vp, aop);
    gemm_tf32<<<gg, bb>>>(aop, Wo, bo, out, 1024, 0, 1.0f);
}

// round 13
// speedup vs baseline: 2.2050x; 1.4657x over previous
#include <cuda_runtime.h>
#include <cstdint>
#include <cstddef>

#define CB 2
#define CN 2048
#define CH 16
#define CD 64
#define CI 1024
#define ATT_SCALE 0.125f

// Scratch (allocation-free rule: __device__ globals)
__device__ float g_q[(size_t)CB * CH * CN * CD];
__device__ float g_k[(size_t)CB * CH * CN * CD];
__device__ float g_v[(size_t)CB * CH * CN * CD];
__device__ float g_ao[(size_t)CB * CN * CI];

__device__ __forceinline__ uint32_t f2tf(float f) {
    uint32_t u;
    asm("cvt.rna.tf32.f32 %0, %1;" : "=r"(u) : "f"(f));
    return u;
}

__device__ __forceinline__ void mma_tf32(float* d, const uint32_t* a,
                                         const uint32_t* b) {
    asm volatile(
        "mma.sync.aligned.m16n8k8.row.col.f32.tf32.tf32.f32 "
        "{%0,%1,%2,%3},{%4,%5,%6,%7},{%8,%9},{%0,%1,%2,%3};"
        : "+f"(d[0]), "+f"(d[1]), "+f"(d[2]), "+f"(d[3])
        : "r"(a[0]), "r"(a[1]), "r"(a[2]), "r"(a[3]), "r"(b[0]), "r"(b[1]));
}

// ---------------------------------------------------------------------------
// tf32 tensor-core GEMM (passing R9 version, unchanged).
// ---------------------------------------------------------------------------
__global__ __launch_bounds__(256) void gemm_tf32(
    const float* __restrict__ A, const float* __restrict__ W,
    const float* __restrict__ bo, float* __restrict__ out,
    int ldw, int mode, float scale)
{
    __shared__ uint32_t As[128 * 36];
    __shared__ uint32_t Bs[32 * 136];

    const int tid  = threadIdx.x;
    const int lane = tid & 31, warp = tid >> 5;
    const int gid = lane >> 2, tig = lane & 3;
    const int wm = warp >> 2, wn = warp & 3;
    const int bm = blockIdx.y << 7, bn = blockIdx.x << 7;

    float acc[4][4][4];
#pragma unroll
    for (int i = 0; i < 4; i++)
#pragma unroll
        for (int j = 0; j < 4; j++)
#pragma unroll
            for (int r = 0; r < 4; r++) acc[i][j][r] = 0.0f;

    for (int k0 = 0; k0 < 1024; k0 += 32) {
#pragma unroll
        for (int t0 = 0; t0 < 4; t0++) {
            int t = tid + (t0 << 8);
            int r = t >> 3, kc = (t & 7) << 2;
            float4 av = *(const float4*)(A + (size_t)(bm + r) * 1024 + k0 + kc);
            uint4 u = make_uint4(f2tf(av.x), f2tf(av.y), f2tf(av.z), f2tf(av.w));
            *(uint4*)&As[r * 36 + kc] = u;
            int kr = t >> 5, nc = (t & 31) << 2;
            float4 wv = *(const float4*)(W + (size_t)(k0 + kr) * ldw + bn + nc);
            uint4 w = make_uint4(f2tf(wv.x), f2tf(wv.y), f2tf(wv.z), f2tf(wv.w));
            *(uint4*)&Bs[kr * 136 + nc] = w;
        }
        __syncthreads();

#pragma unroll
        for (int q = 0; q < 4; q++) {
            const int kq = q << 3;
            uint32_t a[4][4], b[4][2];
#pragma unroll
            for (int sm = 0; sm < 4; sm++) {
                int row = (wm << 6) + (sm << 4) + gid;
                a[sm][0] = As[row * 36 + kq + tig];
                a[sm][1] = As[(row + 8) * 36 + kq + tig];
                a[sm][2] = As[row * 36 + kq + tig + 4];
                a[sm][3] = As[(row + 8) * 36 + kq + tig + 4];
            }
#pragma unroll
            for (int sn = 0; sn < 4; sn++) {
                int col = (wn << 5) + (sn << 3) + gid;
                b[sn][0] = Bs[(kq + tig) * 136 + col];
                b[sn][1] = Bs[(kq + tig + 4) * 136 + col];
            }
#pragma unroll
            for (int sm = 0; sm < 4; sm++)
#pragma unroll
                for (int sn = 0; sn < 4; sn++)
                    mma_tf32(acc[sm][sn], a[sm], b[sn]);
        }
        __syncthreads();
    }

#pragma unroll
    for (int sm = 0; sm < 4; sm++) {
#pragma unroll
        for (int sn = 0; sn < 4; sn++) {
            int col = bn + (wn << 5) + (sn << 3) + (tig << 1);
            float bx = 0.0f, by = 0.0f;
            if (bo) { bx = bo[col]; by = bo[col + 1]; }
#pragma unroll
            for (int half = 0; half < 2; half++) {
                int row = bm + (wm << 6) + (sm << 4) + gid + (half << 3);
                float2 v;
                v.x = acc[sm][sn][half * 2 + 0] * scale + bx;
                v.y = acc[sm][sn][half * 2 + 1] * scale + by;
                if (mode == 0) {
                    *(float2*)(out + (size_t)row * 1024 + col) = v;
                } else {
                    int b_ = row >> 11, n_ = row & 2047;
                    int h_ = col >> 6,  d_ = col & 63;
                    *(float2*)(out + ((((size_t)b_ * CH + h_) * CN + n_) << 6) + d_) = v;
                }
            }
        }
    }
}

// ---------------------------------------------------------------------------
// Flash attention v3: tf32 mma.sync for S=QK^T and O=PV.
// Block = 128 q-rows x head x batch; 16 key tiles of 128.
// Warp grid 4(m) x 2(n). Qs/Ks [row][d] s68; Vt [d][j] s132; Ps [q][k] s132.
// ---------------------------------------------------------------------------
#define ATT_QS 0
#define ATT_KS (ATT_QS + 128 * 68 * 4)
#define ATT_VT (ATT_KS + 128 * 68 * 4)
#define ATT_PS (ATT_VT + 64 * 132 * 4)
#define ATT_MK (ATT_PS + 128 * 132 * 4)
#define ATT_RM (ATT_MK + 512)
#define ATT_RL (ATT_RM + 1024)
#define SMEM_ATT (ATT_RL + 1024)

__global__ __launch_bounds__(256) void attn_kernel(
    const float* __restrict__ bias, const int* __restrict__ mask,
    const float* __restrict__ q, const float* __restrict__ k,
    const float* __restrict__ v, float* __restrict__ aout)
{
    extern __shared__ char smem[];
    uint32_t* Qs = (uint32_t*)(smem + ATT_QS);   // [128][68]
    uint32_t* Ks = (uint32_t*)(smem + ATT_KS);   // [128][68]
    uint32_t* Vt = (uint32_t*)(smem + ATT_VT);   // [64][132]
    uint32_t* Ps = (uint32_t*)(smem + ATT_PS);   // [128][132]
    float*   mko = (float*)(smem + ATT_MK);      // [128]
    float*   redM = (float*)(smem + ATT_RM);     // [2][128]
    float*   redL = (float*)(smem + ATT_RL);     // [2][128]

    const int tid = threadIdx.x;
    const int lane = tid & 31, warp = tid >> 5;
    const int gid = lane >> 2, tig = lane & 3;
    const int wm = warp >> 1, wn = warp & 1;
    const int qt = blockIdx.x, h = blockIdx.y, b = blockIdx.z;

    const float* qb  = q + (((size_t)b * CH + h) * CN + qt * 128) * CD;
    const float* kb0 = k + ((size_t)b * CH + h) * CN * CD;
    const float* vb0 = v + ((size_t)b * CH + h) * CN * CD;

    // Qs fill: [row][d] tf32 (q pre-scaled in projection)
    for (int t = tid; t < 2048; t += 256) {
        int r = t >> 4, c4 = (t & 15) << 2;
        float4 av = *(const float4*)(qb + r * CD + c4);
        *(uint4*)&Qs[r * 68 + c4] =
            make_uint4(f2tf(av.x), f2tf(av.y), f2tf(av.z), f2tf(av.w));
    }

    float m_i[2][2], l_i[2][2], O[2][4][4];
#pragma unroll
    for (int mt = 0; mt < 2; mt++)
#pragma unroll
        for (int hf = 0; hf < 2; hf++) {
            m_i[mt][hf] = -__int_as_float(0x7f800000);
            l_i[mt][hf] = 0.0f;
        }
#pragma unroll
    for (int mt = 0; mt < 2; mt++)
#pragma unroll
        for (int nt = 0; nt < 4; nt++)
#pragma unroll
            for (int r = 0; r < 4; r++) O[mt][nt][r] = 0.0f;

    const float NEG = -3.0e38f;

    for (int jt = 0; jt < 16; jt++) {
        __syncthreads();   // prev PV done with Ks/Vt/Ps
        const float* kb = kb0 + jt * 128 * CD;
        const float* vb = vb0 + jt * 128 * CD;
        for (int t = tid; t < 2048; t += 256) {
            int r = t >> 4, c4 = (t & 15) << 2;
            float4 kv = *(const float4*)(kb + r * CD + c4);
            *(uint4*)&Ks[r * 68 + c4] =
                make_uint4(f2tf(kv.x), f2tf(kv.y), f2tf(kv.z), f2tf(kv.w));
            float4 vv = *(const float4*)(vb + r * CD + c4);
            Vt[(c4 + 0) * 132 + r] = f2tf(vv.x);
            Vt[(c4 + 1) * 132 + r] = f2tf(vv.y);
            Vt[(c4 + 2) * 132 + r] = f2tf(vv.z);
            Vt[(c4 + 3) * 132 + r] = f2tf(vv.w);
        }
        if (tid < 128)
            mko[tid] = mask[b * CN + jt * 128 + tid] ? 0.0f : NEG;
        __syncthreads();

        // ---- S = Q.K^T via tf32 mma ----
        float S[2][8][4];
#pragma unroll
        for (int mt = 0; mt < 2; mt++)
#pragma unroll
            for (int nt = 0; nt < 8; nt++)
#pragma unroll
                for (int r = 0; r < 4; r++) S[mt][nt][r] = 0.0f;

#pragma unroll
        for (int ks = 0; ks < 8; ks++) {
            const int kq = ks << 3;
            uint32_t a[2][4];
#pragma unroll
            for (int mt = 0; mt < 2; mt++) {
                int row = (wm << 5) + (mt << 4) + gid;
                const uint32_t* qp_ = Qs + row * 68 + kq + tig;
                a[mt][0] = qp_[0];
                a[mt][1] = qp_[8 * 68];
                a[mt][2] = qp_[4];
                a[mt][3] = qp_[8 * 68 + 4];
            }
#pragma unroll
            for (int nt = 0; nt < 8; nt++) {
                int col = (wn << 6) + (nt << 3) + gid;
                uint32_t bb[2];
                bb[0] = Ks[col * 68 + kq + tig];
                bb[1] = Ks[col * 68 + kq + tig + 4];
                mma_tf32(S[0][nt], a[0], bb);
                mma_tf32(S[1][nt], a[1], bb);
            }
        }

        // ---- bias + mask (frag layout: rows gid/gid+8, cols 2tig/2tig+1) ----
        float mkc[8][2];
#pragma unroll
        for (int nt = 0; nt < 8; nt++) {
            float2 m2 = *(float2*)&mko[(wn << 6) + (nt << 3) + (tig << 1)];
            mkc[nt][0] = m2.x; mkc[nt][1] = m2.y;
        }
        const size_t brow0 = ((size_t)b * CN + qt * 128) * CN + jt * 128 + (wn << 6);
#pragma unroll
        for (int mt = 0; mt < 2; mt++)
#pragma unroll
            for (int hf = 0; hf < 2; hf++) {
                int rloc = (wm << 5) + (mt << 4) + gid + (hf << 3);
                const float* bp = bias + brow0 + (size_t)rloc * CN + (tig << 1);
#pragma unroll
                for (int nt = 0; nt < 8; nt++) {
                    float2 bv = *(const float2*)(bp + (nt << 3));
                    S[mt][nt][hf * 2 + 0] += bv.x + mkc[nt][0];
                    S[mt][nt][hf * 2 + 1] += bv.y + mkc[nt][1];
                }
            }

        // ---- row max (intra-warp over tig, then cross-warp via smem) ----
#pragma unroll
        for (int mt = 0; mt < 2; mt++)
#pragma unroll
            for (int hf = 0; hf < 2; hf++) {
                float mx = S[mt][0][hf * 2];
#pragma unroll
                for (int nt = 0; nt < 8; nt++) {
                    mx = fmaxf(mx, S[mt][nt][hf * 2 + 0]);
                    mx = fmaxf(mx, S[mt][nt][hf * 2 + 1]);
                }
                mx = fmaxf(mx, __shfl_xor_sync(0xffffffffu, mx, 1));
                mx = fmaxf(mx, __shfl_xor_sync(0xffffffffu, mx, 2));
                if (tig == 0) {
                    int rloc = (wm << 5) + (mt << 4) + gid + (hf << 3);
                    redM[(wn << 7) + rloc] = mx;
                }
            }
        __syncthreads();

        // ---- exp + P store + partial sums ----
        float alpha[2][2], rs[2][2];
#pragma unroll
        for (int mt = 0; mt < 2; mt++)
#pragma unroll
            for (int hf = 0; hf < 2; hf++) {
                int rloc = (wm << 5) + (mt << 4) + gid + (hf << 3);
                float rowm = fmaxf(redM[rloc], redM[128 + rloc]);
                float mnew = fmaxf(m_i[mt][hf], rowm);
                alpha[mt][hf] = __expf(m_i[mt][hf] - mnew);
                m_i[mt][hf] = mnew;
                float s = 0.0f;
#pragma unroll
                for (int nt = 0; nt < 8; nt++) {
                    float e0 = __expf(S[mt][nt][hf * 2 + 0] - mnew);
                    float e1 = __expf(S[mt][nt][hf * 2 + 1] - mnew);
                    s += e0 + e1;
                    Ps[rloc * 132 + (wn << 6) + (nt << 3) + (tig << 1)] = f2tf(e0);
                    Ps[rloc * 132 + (wn << 6) + (nt << 3) + (tig << 1) + 1] = f2tf(e1);
                }
                s += __shfl_xor_sync(0xffffffffu, s, 1);
                s += __shfl_xor_sync(0xffffffffu, s, 2);
                rs[mt][hf] = s;
                if (tig == 0) redL[(wn << 7) + rloc] = s;
            }
        // rescale O by alpha
#pragma unroll
        for (int mt = 0; mt < 2; mt++)
#pragma unroll
            for (int nt = 0; nt < 4; nt++) {
                O[mt][nt][0] *= alpha[mt][0];
                O[mt][nt][1] *= alpha[mt][0];
                O[mt][nt][2] *= alpha[mt][1];
                O[mt][nt][3] *= alpha[mt][1];
            }
        __syncthreads();

        // ---- l update (full row sums) ----
#pragma unroll
        for (int mt = 0; mt < 2; mt++)
#pragma unroll
            for (int hf = 0; hf < 2; hf++) {
                int rloc = (wm << 5) + (mt << 4) + gid + (hf << 3);
                l_i[mt][hf] = l_i[mt][hf] * alpha[mt][hf]
                            + redL[rloc] + redL[128 + rloc];
            }

        // ---- O += P @ V via tf32 mma ----
#pragma unroll
        for (int ks = 0; ks < 16; ks++) {
            const int kq = ks << 3;
            uint32_t a[2][4];
#pragma unroll
            for (int mt = 0; mt < 2; mt++) {
                int row = (wm << 5) + (mt << 4) + gid;
                const uint32_t* pp = Ps + row * 132 + kq + tig;
                a[mt][0] = pp[0];
                a[mt][1] = pp[8 * 132];
                a[mt][2] = pp[4];
                a[mt][3] = pp[8 * 132 + 4];
            }
#pragma unroll
            for (int nt = 0; nt < 4; nt++) {
                int col = (wn << 5) + (nt << 3) + gid;
                uint32_t bb[2];
                bb[0] = Vt[col * 132 + kq + tig];
                bb[1] = Vt[col * 132 + kq + tig + 4];
                mma_tf32(O[0][nt], a[0], bb);
                mma_tf32(O[1][nt], a[1], bb);
            }
        }
    }

    // ---- finalize ----
#pragma unroll
    for (int mt = 0; mt < 2; mt++)
#pragma unroll
        for (int hf = 0; hf < 2; hf++) {
            int rloc = (wm << 5) + (mt << 4) + gid + (hf << 3);
            int row = qt * 128 + rloc;
            float inv = 1.0f / l_i[mt][hf];
#pragma unroll
            for (int nt = 0; nt < 4; nt++) {
                int dcol = (wn << 5) + (nt << 3) + (tig << 1);
                float2 o2;
                o2.x = O[mt][nt][hf * 2 + 0] * inv;
                o2.y = O[mt][nt][hf * 2 + 1] * inv;
                *(float2*)(aout + ((size_t)b * CN + row) * CI + h * 64 + dcol) = o2;
            }
        }
}

// ---------------------------------------------------------------------------
extern "C" void kernel_launch(void* const* d_in, const int* in_sizes, int n_in,
                              void* d_out, int out_size) {
    (void)in_sizes; (void)n_in; (void)out_size;
    const float* x    = (const float*)d_in[0];
    const float* bias = (const float*)d_in[1];
    const int*   mask = (const int*)d_in[2];
    const float* Wq   = (const float*)d_in[3];
    const float* Wkv  = (const float*)d_in[4];
    const float* Wo   = (const float*)d_in[5];
    const float* bo   = (const float*)d_in[6];
    float* out = (float*)d_out;

    float *qp, *kp, *vp, *aop;
    cudaGetSymbolAddress((void**)&qp, g_q);
    cudaGetSymbolAddress((void**)&kp, g_k);
    cudaGetSymbolAddress((void**)&vp, g_v);
    cudaGetSymbolAddress((void**)&aop, g_ao);

    cudaFuncSetAttribute(attn_kernel,
                         cudaFuncAttributeMaxDynamicSharedMemorySize, SMEM_ATT);

    dim3 gg(8, 32), bb(256);
    gemm_tf32<<<gg, bb>>>(x, Wq, nullptr, qp, 1024, 1, ATT_SCALE);
    gemm_tf32<<<gg, bb>>>(x, Wkv, nullptr, kp, 2048, 1, 1.0f);
    gemm_tf32<<<gg, bb>>>(x, Wkv + 1024, nullptr, vp, 2048, 1, 1.0f);
    attn_kernel<<<dim3(16, 16, 2), bb, SMEM_ATT>>>(bias, mask, qp, kp, vp, aop);
    gemm_tf32<<<gg, bb>>>(aop, Wo, bo, out, 1024, 0, 1.0f);
}

// round 14
// speedup vs baseline: 2.4961x; 1.1320x over previous
#include <cuda_runtime.h>
#include <cstdint>
#include <cstddef>

#define CB 2
#define CN 2048
#define CH 16
#define CD 64
#define CI 1024
#define ATT_SCALE 0.125f

// Scratch (allocation-free rule: __device__ globals)
__device__ float g_q[(size_t)CB * CH * CN * CD];
__device__ float g_k[(size_t)CB * CH * CN * CD];
__device__ float g_v[(size_t)CB * CH * CN * CD];
__device__ float g_ao[(size_t)CB * CN * CI];

__device__ __forceinline__ uint32_t f2tf(float f) {
    uint32_t u;
    asm("cvt.rna.tf32.f32 %0, %1;" : "=r"(u) : "f"(f));
    return u;
}

__device__ __forceinline__ void mma_tf32(float* d, const uint32_t* a,
                                         const uint32_t* b) {
    asm volatile(
        "mma.sync.aligned.m16n8k8.row.col.f32.tf32.tf32.f32 "
        "{%0,%1,%2,%3},{%4,%5,%6,%7},{%8,%9},{%0,%1,%2,%3};"
        : "+f"(d[0]), "+f"(d[1]), "+f"(d[2]), "+f"(d[3])
        : "r"(a[0]), "r"(a[1]), "r"(a[2]), "r"(a[3]), "r"(b[0]), "r"(b[1]));
}

// ---------------------------------------------------------------------------
// tf32 tensor-core GEMM (passing R9 version, unchanged).
// ---------------------------------------------------------------------------
__global__ __launch_bounds__(256) void gemm_tf32(
    const float* __restrict__ A, const float* __restrict__ W,
    const float* __restrict__ bo, float* __restrict__ out,
    int ldw, int mode, float scale)
{
    __shared__ uint32_t As[128 * 36];
    __shared__ uint32_t Bs[32 * 136];

    const int tid  = threadIdx.x;
    const int lane = tid & 31, warp = tid >> 5;
    const int gid = lane >> 2, tig = lane & 3;
    const int wm = warp >> 2, wn = warp & 3;
    const int bm = blockIdx.y << 7, bn = blockIdx.x << 7;

    float acc[4][4][4];
#pragma unroll
    for (int i = 0; i < 4; i++)
#pragma unroll
        for (int j = 0; j < 4; j++)
#pragma unroll
            for (int r = 0; r < 4; r++) acc[i][j][r] = 0.0f;

    for (int k0 = 0; k0 < 1024; k0 += 32) {
#pragma unroll
        for (int t0 = 0; t0 < 4; t0++) {
            int t = tid + (t0 << 8);
            int r = t >> 3, kc = (t & 7) << 2;
            float4 av = *(const float4*)(A + (size_t)(bm + r) * 1024 + k0 + kc);
            uint4 u = make_uint4(f2tf(av.x), f2tf(av.y), f2tf(av.z), f2tf(av.w));
            *(uint4*)&As[r * 36 + kc] = u;
            int kr = t >> 5, nc = (t & 31) << 2;
            float4 wv = *(const float4*)(W + (size_t)(k0 + kr) * ldw + bn + nc);
            uint4 w = make_uint4(f2tf(wv.x), f2tf(wv.y), f2tf(wv.z), f2tf(wv.w));
            *(uint4*)&Bs[kr * 136 + nc] = w;
        }
        __syncthreads();

#pragma unroll
        for (int q = 0; q < 4; q++) {
            const int kq = q << 3;
            uint32_t a[4][4], b[4][2];
#pragma unroll
            for (int sm = 0; sm < 4; sm++) {
                int row = (wm << 6) + (sm << 4) + gid;
                a[sm][0] = As[row * 36 + kq + tig];
                a[sm][1] = As[(row + 8) * 36 + kq + tig];
                a[sm][2] = As[row * 36 + kq + tig + 4];
                a[sm][3] = As[(row + 8) * 36 + kq + tig + 4];
            }
#pragma unroll
            for (int sn = 0; sn < 4; sn++) {
                int col = (wn << 5) + (sn << 3) + gid;
                b[sn][0] = Bs[(kq + tig) * 136 + col];
                b[sn][1] = Bs[(kq + tig + 4) * 136 + col];
            }
#pragma unroll
            for (int sm = 0; sm < 4; sm++)
#pragma unroll
                for (int sn = 0; sn < 4; sn++)
                    mma_tf32(acc[sm][sn], a[sm], b[sn]);
        }
        __syncthreads();
    }

#pragma unroll
    for (int sm = 0; sm < 4; sm++) {
#pragma unroll
        for (int sn = 0; sn < 4; sn++) {
            int col = bn + (wn << 5) + (sn << 3) + (tig << 1);
            float bx = 0.0f, by = 0.0f;
            if (bo) { bx = bo[col]; by = bo[col + 1]; }
#pragma unroll
            for (int half = 0; half < 2; half++) {
                int row = bm + (wm << 6) + (sm << 4) + gid + (half << 3);
                float2 v;
                v.x = acc[sm][sn][half * 2 + 0] * scale + bx;
                v.y = acc[sm][sn][half * 2 + 1] * scale + by;
                if (mode == 0) {
                    *(float2*)(out + (size_t)row * 1024 + col) = v;
                } else {
                    int b_ = row >> 11, n_ = row & 2047;
                    int h_ = col >> 6,  d_ = col & 63;
                    *(float2*)(out + ((((size_t)b_ * CH + h_) * CN + n_) << 6) + d_) = v;
                }
            }
        }
    }
}

// ---------------------------------------------------------------------------
// Flash attention v4: tf32 mma, 128q x 64k tiles, 2 CTAs/SM (104 KB smem).
// Warp grid 4(m) x 2(n). Qs/Ks [row][d] s68; Vt [d][j] s68; Ps [q][k] s68.
// ---------------------------------------------------------------------------
#define ATT_QS 0
#define ATT_KS (ATT_QS + 128 * 68 * 4)
#define ATT_VT (ATT_KS + 64 * 68 * 4)
#define ATT_PS (ATT_VT + 64 * 68 * 4)
#define ATT_MK (ATT_PS + 128 * 68 * 4)
#define ATT_RM (ATT_MK + 256)
#define ATT_RL (ATT_RM + 1024)
#define SMEM_ATT (ATT_RL + 1024)   // 106752 B

__global__ __launch_bounds__(256, 2) void attn_kernel(
    const float* __restrict__ bias, const int* __restrict__ mask,
    const float* __restrict__ q, const float* __restrict__ k,
    const float* __restrict__ v, float* __restrict__ aout)
{
    extern __shared__ char smem[];
    uint32_t* Qs = (uint32_t*)(smem + ATT_QS);   // [128][68]
    uint32_t* Ks = (uint32_t*)(smem + ATT_KS);   // [64][68]
    uint32_t* Vt = (uint32_t*)(smem + ATT_VT);   // [64][68]
    uint32_t* Ps = (uint32_t*)(smem + ATT_PS);   // [128][68]
    float*   mko = (float*)(smem + ATT_MK);      // [64]
    float*   redM = (float*)(smem + ATT_RM);     // [2][128]
    float*   redL = (float*)(smem + ATT_RL);     // [2][128]

    const int tid = threadIdx.x;
    const int lane = tid & 31, warp = tid >> 5;
    const int gid = lane >> 2, tig = lane & 3;
    const int wm = warp >> 1, wn = warp & 1;
    const int qt = blockIdx.x, h = blockIdx.y, b = blockIdx.z;

    const float* qb  = q + (((size_t)b * CH + h) * CN + qt * 128) * CD;
    const float* kb0 = k + ((size_t)b * CH + h) * CN * CD;
    const float* vb0 = v + ((size_t)b * CH + h) * CN * CD;

    // Qs fill: [row][d] tf32 (q pre-scaled in projection)
    for (int t = tid; t < 2048; t += 256) {
        int r = t >> 4, c4 = (t & 15) << 2;
        float4 av = *(const float4*)(qb + r * CD + c4);
        *(uint4*)&Qs[r * 68 + c4] =
            make_uint4(f2tf(av.x), f2tf(av.y), f2tf(av.z), f2tf(av.w));
    }

    float m_i[2][2], l_i[2][2], O[2][4][4];
#pragma unroll
    for (int mt = 0; mt < 2; mt++)
#pragma unroll
        for (int hf = 0; hf < 2; hf++) {
            m_i[mt][hf] = -__int_as_float(0x7f800000);
            l_i[mt][hf] = 0.0f;
        }
#pragma unroll
    for (int mt = 0; mt < 2; mt++)
#pragma unroll
        for (int nt = 0; nt < 4; nt++)
#pragma unroll
            for (int r = 0; r < 4; r++) O[mt][nt][r] = 0.0f;

    const float NEG = -3.0e38f;

    for (int jt = 0; jt < 32; jt++) {
        __syncthreads();   // prev PV done with Ks/Vt/Ps
        const float* kb = kb0 + jt * 64 * CD;
        const float* vb = vb0 + jt * 64 * CD;
        for (int t = tid; t < 1024; t += 256) {
            int r = t >> 4, c4 = (t & 15) << 2;
            float4 kv = *(const float4*)(kb + r * CD + c4);
            *(uint4*)&Ks[r * 68 + c4] =
                make_uint4(f2tf(kv.x), f2tf(kv.y), f2tf(kv.z), f2tf(kv.w));
            float4 vv = *(const float4*)(vb + r * CD + c4);
            Vt[(c4 + 0) * 68 + r] = f2tf(vv.x);
            Vt[(c4 + 1) * 68 + r] = f2tf(vv.y);
            Vt[(c4 + 2) * 68 + r] = f2tf(vv.z);
            Vt[(c4 + 3) * 68 + r] = f2tf(vv.w);
        }
        if (tid < 64)
            mko[tid] = mask[b * CN + jt * 64 + tid] ? 0.0f : NEG;
        __syncthreads();

        // ---- S = Q.K^T via tf32 mma (128x64 tile) ----
        float S[2][4][4];
#pragma unroll
        for (int mt = 0; mt < 2; mt++)
#pragma unroll
            for (int nt = 0; nt < 4; nt++)
#pragma unroll
                for (int r = 0; r < 4; r++) S[mt][nt][r] = 0.0f;

#pragma unroll
        for (int ks = 0; ks < 8; ks++) {
            const int kq = ks << 3;
            uint32_t a[2][4];
#pragma unroll
            for (int mt = 0; mt < 2; mt++) {
                int row = (wm << 5) + (mt << 4) + gid;
                const uint32_t* qp_ = Qs + row * 68 + kq + tig;
                a[mt][0] = qp_[0];
                a[mt][1] = qp_[8 * 68];
                a[mt][2] = qp_[4];
                a[mt][3] = qp_[8 * 68 + 4];
            }
#pragma unroll
            for (int nt = 0; nt < 4; nt++) {
                int col = (wn << 5) + (nt << 3) + gid;
                uint32_t bb[2];
                bb[0] = Ks[col * 68 + kq + tig];
                bb[1] = Ks[col * 68 + kq + tig + 4];
                mma_tf32(S[0][nt], a[0], bb);
                mma_tf32(S[1][nt], a[1], bb);
            }
        }

        // ---- bias + mask (frag: rows gid/gid+8, cols 2tig/2tig+1) ----
        float mkc[4][2];
#pragma unroll
        for (int nt = 0; nt < 4; nt++) {
            float2 m2 = *(float2*)&mko[(wn << 5) + (nt << 3) + (tig << 1)];
            mkc[nt][0] = m2.x; mkc[nt][1] = m2.y;
        }
        const size_t brow0 = ((size_t)b * CN + qt * 128) * CN + jt * 64 + (wn << 5);
#pragma unroll
        for (int mt = 0; mt < 2; mt++)
#pragma unroll
            for (int hf = 0; hf < 2; hf++) {
                int rloc = (wm << 5) + (mt << 4) + gid + (hf << 3);
                const float* bp = bias + brow0 + (size_t)rloc * CN + (tig << 1);
#pragma unroll
                for (int nt = 0; nt < 4; nt++) {
                    float2 bv = *(const float2*)(bp + (nt << 3));
                    S[mt][nt][hf * 2 + 0] += bv.x + mkc[nt][0];
                    S[mt][nt][hf * 2 + 1] += bv.y + mkc[nt][1];
                }
            }

        // ---- row max (intra-warp over tig, then cross-warp via smem) ----
#pragma unroll
        for (int mt = 0; mt < 2; mt++)
#pragma unroll
            for (int hf = 0; hf < 2; hf++) {
                float mx = S[mt][0][hf * 2];
#pragma unroll
                for (int nt = 0; nt < 4; nt++) {
                    mx = fmaxf(mx, S[mt][nt][hf * 2 + 0]);
                    mx = fmaxf(mx, S[mt][nt][hf * 2 + 1]);
                }
                mx = fmaxf(mx, __shfl_xor_sync(0xffffffffu, mx, 1));
                mx = fmaxf(mx, __shfl_xor_sync(0xffffffffu, mx, 2));
                if (tig == 0) {
                    int rloc = (wm << 5) + (mt << 4) + gid + (hf << 3);
                    redM[(wn << 7) + rloc] = mx;
                }
            }
        __syncthreads();

        // ---- exp + P store + partial sums ----
        float alpha[2][2];
#pragma unroll
        for (int mt = 0; mt < 2; mt++)
#pragma unroll
            for (int hf = 0; hf < 2; hf++) {
                int rloc = (wm << 5) + (mt << 4) + gid + (hf << 3);
                float rowm = fmaxf(redM[rloc], redM[128 + rloc]);
                float mnew = fmaxf(m_i[mt][hf], rowm);
                alpha[mt][hf] = __expf(m_i[mt][hf] - mnew);
                m_i[mt][hf] = mnew;
                float s = 0.0f;
#pragma unroll
                for (int nt = 0; nt < 4; nt++) {
                    float e0 = __expf(S[mt][nt][hf * 2 + 0] - mnew);
                    float e1 = __expf(S[mt][nt][hf * 2 + 1] - mnew);
                    s += e0 + e1;
                    uint32_t* pp = Ps + rloc * 68 + (wn << 5) + (nt << 3) + (tig << 1);
                    pp[0] = f2tf(e0);
                    pp[1] = f2tf(e1);
                }
                s += __shfl_xor_sync(0xffffffffu, s, 1);
                s += __shfl_xor_sync(0xffffffffu, s, 2);
                if (tig == 0) redL[(wn << 7) + rloc] = s;
            }
        // rescale O by alpha
#pragma unroll
        for (int mt = 0; mt < 2; mt++)
#pragma unroll
            for (int nt = 0; nt < 4; nt++) {
                O[mt][nt][0] *= alpha[mt][0];
                O[mt][nt][1] *= alpha[mt][0];
                O[mt][nt][2] *= alpha[mt][1];
                O[mt][nt][3] *= alpha[mt][1];
            }
        __syncthreads();

        // ---- l update (full row sums) ----
#pragma unroll
        for (int mt = 0; mt < 2; mt++)
#pragma unroll
            for (int hf = 0; hf < 2; hf++) {
                int rloc = (wm << 5) + (mt << 4) + gid + (hf << 3);
                l_i[mt][hf] = l_i[mt][hf] * alpha[mt][hf]
                            + redL[rloc] + redL[128 + rloc];
            }

        // ---- O += P @ V via tf32 mma ----
#pragma unroll
        for (int ks = 0; ks < 8; ks++) {
            const int kq = ks << 3;
            uint32_t a[2][4];
#pragma unroll
            for (int mt = 0; mt < 2; mt++) {
                int row = (wm << 5) + (mt << 4) + gid;
                const uint32_t* pp = Ps + row * 68 + kq + tig;
                a[mt][0] = pp[0];
                a[mt][1] = pp[8 * 68];
                a[mt][2] = pp[4];
                a[mt][3] = pp[8 * 68 + 4];
            }
#pragma unroll
            for (int nt = 0; nt < 4; nt++) {
                int col = (wn << 5) + (nt << 3) + gid;
                uint32_t bb[2];
                bb[0] = Vt[col * 68 + kq + tig];
                bb[1] = Vt[col * 68 + kq + tig + 4];
                mma_tf32(O[0][nt], a[0], bb);
                mma_tf32(O[1][nt], a[1], bb);
            }
        }
    }

    // ---- finalize ----
#pragma unroll
    for (int mt = 0; mt < 2; mt++)
#pragma unroll
        for (int hf = 0; hf < 2; hf++) {
            int rloc = (wm << 5) + (mt << 4) + gid + (hf << 3);
            int row = qt * 128 + rloc;
            float inv = 1.0f / l_i[mt][hf];
#pragma unroll
            for (int nt = 0; nt < 4; nt++) {
                int dcol = (wn << 5) + (nt << 3) + (tig << 1);
                float2 o2;
                o2.x = O[mt][nt][hf * 2 + 0] * inv;
                o2.y = O[mt][nt][hf * 2 + 1] * inv;
                *(float2*)(aout + ((size_t)b * CN + row) * CI + h * 64 + dcol) = o2;
            }
        }
}

// ---------------------------------------------------------------------------
extern "C" void kernel_launch(void* const* d_in, const int* in_sizes, int n_in,
                              void* d_out, int out_size) {
    (void)in_sizes; (void)n_in; (void)out_size;
    const float* x    = (const float*)d_in[0];
    const float* bias = (const float*)d_in[1];
    const int*   mask = (const int*)d_in[2];
    const float* Wq   = (const float*)d_in[3];
    const float* Wkv  = (const float*)d_in[4];
    const float* Wo   = (const float*)d_in[5];
    const float* bo   = (const float*)d_in[6];
    float* out = (float*)d_out;

    float *qp, *kp, *vp, *aop;
    cudaGetSymbolAddress((void**)&qp, g_q);
    cudaGetSymbolAddress((void**)&kp, g_k);
    cudaGetSymbolAddress((void**)&vp, g_v);
    cudaGetSymbolAddress((void**)&aop, g_ao);

    cudaFuncSetAttribute(attn_kernel,
                         cudaFuncAttributeMaxDynamicSharedMemorySize, SMEM_ATT);

    dim3 gg(8, 32), bb(256);
    gemm_tf32<<<gg, bb>>>(x, Wq, nullptr, qp, 1024, 1, ATT_SCALE);
    gemm_tf32<<<gg, bb>>>(x, Wkv, nullptr, kp, 2048, 1, 1.0f);
    gemm_tf32<<<gg, bb>>>(x, Wkv + 1024, nullptr, vp, 2048, 1, 1.0f);
    attn_kernel<<<dim3(16, 16, 2), bb, SMEM_ATT>>>(bias, mask, qp, kp, vp, aop);
    gemm_tf32<<<gg, bb>>>(aop, Wo, bo, out, 1024, 0, 1.0f);
}

// round 16
// speedup vs baseline: 2.8477x; 1.1408x over previous
#include <cuda_runtime.h>
#include <cstdint>
#include <cstddef>

#define CB 2
#define CN 2048
#define CH 16
#define CD 64
#define CI 1024
#define ATT_SCALE 0.125f

// Scratch (allocation-free rule: __device__ globals)
__device__ float g_q[(size_t)CB * CH * CN * CD];
__device__ float g_k[(size_t)CB * CH * CN * CD];
__device__ float g_v[(size_t)CB * CH * CN * CD];
__device__ float g_ao[(size_t)CB * CN * CI];

__device__ __forceinline__ uint32_t f2tf(float f) {
    uint32_t u;
    asm("cvt.rna.tf32.f32 %0, %1;" : "=r"(u) : "f"(f));
    return u;
}

__device__ __forceinline__ void mma_tf32(float* d, const uint32_t* a,
                                         const uint32_t* b) {
    asm volatile(
        "mma.sync.aligned.m16n8k8.row.col.f32.tf32.tf32.f32 "
        "{%0,%1,%2,%3},{%4,%5,%6,%7},{%8,%9},{%0,%1,%2,%3};"
        : "+f"(d[0]), "+f"(d[1]), "+f"(d[2]), "+f"(d[3])
        : "r"(a[0]), "r"(a[1]), "r"(a[2]), "r"(a[3]), "r"(b[0]), "r"(b[1]));
}

// ---------------------------------------------------------------------------
// tf32 tensor-core GEMM (passing R9 version, unchanged).
// ---------------------------------------------------------------------------
__global__ __launch_bounds__(256) void gemm_tf32(
    const float* __restrict__ A, const float* __restrict__ W,
    const float* __restrict__ bo, float* __restrict__ out,
    int ldw, int mode, float scale)
{
    __shared__ uint32_t As[128 * 36];
    __shared__ uint32_t Bs[32 * 136];

    const int tid  = threadIdx.x;
    const int lane = tid & 31, warp = tid >> 5;
    const int gid = lane >> 2, tig = lane & 3;
    const int wm = warp >> 2, wn = warp & 3;
    const int bm = blockIdx.y << 7, bn = blockIdx.x << 7;

    float acc[4][4][4];
#pragma unroll
    for (int i = 0; i < 4; i++)
#pragma unroll
        for (int j = 0; j < 4; j++)
#pragma unroll
            for (int r = 0; r < 4; r++) acc[i][j][r] = 0.0f;

    for (int k0 = 0; k0 < 1024; k0 += 32) {
#pragma unroll
        for (int t0 = 0; t0 < 4; t0++) {
            int t = tid + (t0 << 8);
            int r = t >> 3, kc = (t & 7) << 2;
            float4 av = *(const float4*)(A + (size_t)(bm + r) * 1024 + k0 + kc);
            uint4 u = make_uint4(f2tf(av.x), f2tf(av.y), f2tf(av.z), f2tf(av.w));
            *(uint4*)&As[r * 36 + kc] = u;
            int kr = t >> 5, nc = (t & 31) << 2;
            float4 wv = *(const float4*)(W + (size_t)(k0 + kr) * ldw + bn + nc);
            uint4 w = make_uint4(f2tf(wv.x), f2tf(wv.y), f2tf(wv.z), f2tf(wv.w));
            *(uint4*)&Bs[kr * 136 + nc] = w;
        }
        __syncthreads();

#pragma unroll
        for (int q = 0; q < 4; q++) {
            const int kq = q << 3;
            uint32_t a[4][4], b[4][2];
#pragma unroll
            for (int sm = 0; sm < 4; sm++) {
                int row = (wm << 6) + (sm << 4) + gid;
                a[sm][0] = As[row * 36 + kq + tig];
                a[sm][1] = As[(row + 8) * 36 + kq + tig];
                a[sm][2] = As[row * 36 + kq + tig + 4];
                a[sm][3] = As[(row + 8) * 36 + kq + tig + 4];
            }
#pragma unroll
            for (int sn = 0; sn < 4; sn++) {
                int col = (wn << 5) + (sn << 3) + gid;
                b[sn][0] = Bs[(kq + tig) * 136 + col];
                b[sn][1] = Bs[(kq + tig + 4) * 136 + col];
            }
#pragma unroll
            for (int sm = 0; sm < 4; sm++)
#pragma unroll
                for (int sn = 0; sn < 4; sn++)
                    mma_tf32(acc[sm][sn], a[sm], b[sn]);
        }
        __syncthreads();
    }

#pragma unroll
    for (int sm = 0; sm < 4; sm++) {
#pragma unroll
        for (int sn = 0; sn < 4; sn++) {
            int col = bn + (wn << 5) + (sn << 3) + (tig << 1);
            float bx = 0.0f, by = 0.0f;
            if (bo) { bx = bo[col]; by = bo[col + 1]; }
#pragma unroll
            for (int half = 0; half < 2; half++) {
                int row = bm + (wm << 6) + (sm << 4) + gid + (half << 3);
                float2 v;
                v.x = acc[sm][sn][half * 2 + 0] * scale + bx;
                v.y = acc[sm][sn][half * 2 + 1] * scale + by;
                if (mode == 0) {
                    *(float2*)(out + (size_t)row * 1024 + col) = v;
                } else {
                    int b_ = row >> 11, n_ = row & 2047;
                    int h_ = col >> 6,  d_ = col & 63;
                    *(float2*)(out + ((((size_t)b_ * CH + h_) * CN + n_) << 6) + d_) = v;
                }
            }
        }
    }
}

// ---------------------------------------------------------------------------
// Flash attention v5: warp-independent tiles.
// Warp grid 8(m)x1(n): each warp owns 16 q-rows x 64-key tile.
// Warp-local softmax (quad shuffles). P->A-frag via intra-warp shuffles
// (no Ps smem). V natural [j][d] stride 72 (conflict-free B-frags).
// 2 syncthreads per jt. ~71 KB smem, 2 CTAs/SM.
// ---------------------------------------------------------------------------
#define ATT_QS 0
#define ATT_KS (ATT_QS + 128 * 68 * 4)    // 34816
#define ATT_VS (ATT_KS + 64 * 68 * 4)     // +17408
#define ATT_MK (ATT_VS + 64 * 72 * 4)     // +18432
#define SMEM_ATT (ATT_MK + 256)           // 70912 B

__global__ __launch_bounds__(256, 2) void attn_kernel(
    const float* __restrict__ bias, const int* __restrict__ mask,
    const float* __restrict__ q, const float* __restrict__ k,
    const float* __restrict__ v, float* __restrict__ aout)
{
    extern __shared__ char smem[];
    uint32_t* Qs = (uint32_t*)(smem + ATT_QS);   // [128][68] tf32
    uint32_t* Ks = (uint32_t*)(smem + ATT_KS);   // [64][68]  tf32
    uint32_t* Vs = (uint32_t*)(smem + ATT_VS);   // [64][72]  tf32, natural [j][d]
    float*   mko = (float*)(smem + ATT_MK);      // [64]

    const int tid = threadIdx.x;
    const int lane = tid & 31, warp = tid >> 5;
    const int gid = lane >> 2, tig = lane & 3;
    const int W16 = warp << 4;                   // warp's q-row base
    const int qt = blockIdx.x, h = blockIdx.y, b = blockIdx.z;

    const float* qb  = q + (((size_t)b * CH + h) * CN + qt * 128) * CD;
    const float* kb0 = k + ((size_t)b * CH + h) * CN * CD;
    const float* vb0 = v + ((size_t)b * CH + h) * CN * CD;

    // Qs fill: [row][d] tf32 (q pre-scaled in projection)
    for (int t = tid; t < 2048; t += 256) {
        int r = t >> 4, c4 = (t & 15) << 2;
        float4 av = *(const float4*)(qb + r * CD + c4);
        *(uint4*)&Qs[r * 68 + c4] =
            make_uint4(f2tf(av.x), f2tf(av.y), f2tf(av.z), f2tf(av.w));
    }

    float m_i[2], l_i[2], O[8][4];
    m_i[0] = m_i[1] = -__int_as_float(0x7f800000);
    l_i[0] = l_i[1] = 0.0f;
#pragma unroll
    for (int nt = 0; nt < 8; nt++)
#pragma unroll
        for (int r = 0; r < 4; r++) O[nt][r] = 0.0f;

    const float NEG = -3.0e38f;

    for (int jt = 0; jt < 32; jt++) {
        __syncthreads();   // prev S/PV done reading Ks/Vs

        // ---- bias prefetch (consumed after S-MMA; latency hidden) ----
        float2 breg[2][8];
        const float* bp0 = bias + ((size_t)b * CN + qt * 128 + W16 + gid) * CN
                         + jt * 64 + (tig << 1);
#pragma unroll
        for (int nt = 0; nt < 8; nt++) breg[0][nt] = *(const float2*)(bp0 + (nt << 3));
        const float* bp1 = bp0 + 8 * CN;
#pragma unroll
        for (int nt = 0; nt < 8; nt++) breg[1][nt] = *(const float2*)(bp1 + (nt << 3));

        // ---- K/V fill ----
        const float* kb = kb0 + jt * 64 * CD;
        const float* vb = vb0 + jt * 64 * CD;
#pragma unroll
        for (int i = 0; i < 4; i++) {
            int t = tid + (i << 8);
            int r = t >> 4, c4 = (t & 15) << 2;
            float4 kv = *(const float4*)(kb + r * CD + c4);
            *(uint4*)&Ks[r * 68 + c4] =
                make_uint4(f2tf(kv.x), f2tf(kv.y), f2tf(kv.z), f2tf(kv.w));
            float4 vv = *(const float4*)(vb + r * CD + c4);
            *(uint4*)&Vs[r * 72 + c4] =
                make_uint4(f2tf(vv.x), f2tf(vv.y), f2tf(vv.z), f2tf(vv.w));
        }
        if (tid < 64)
            mko[tid] = mask[b * CN + jt * 64 + tid] ? 0.0f : NEG;
        __syncthreads();

        // ---- S = Q.K^T (16x64 per warp) ----
        float S[8][4];
#pragma unroll
        for (int nt = 0; nt < 8; nt++)
#pragma unroll
            for (int r = 0; r < 4; r++) S[nt][r] = 0.0f;

#pragma unroll
        for (int ks = 0; ks < 8; ks++) {
            const int kq = ks << 3;
            uint32_t a[4];
            const uint32_t* qp_ = Qs + (W16 + gid) * 68 + kq + tig;
            a[0] = qp_[0];
            a[1] = qp_[8 * 68];
            a[2] = qp_[4];
            a[3] = qp_[8 * 68 + 4];
#pragma unroll
            for (int nt = 0; nt < 8; nt++) {
                int col = (nt << 3) + gid;
                uint32_t bb[2];
                bb[0] = Ks[col * 68 + kq + tig];
                bb[1] = Ks[col * 68 + kq + tig + 4];
                mma_tf32(S[nt], a, bb);
            }
        }

        // ---- bias + mask ----
#pragma unroll
        for (int nt = 0; nt < 8; nt++) {
            float2 mk = *(float2*)&mko[(nt << 3) + (tig << 1)];
            S[nt][0] += breg[0][nt].x + mk.x;
            S[nt][1] += breg[0][nt].y + mk.y;
            S[nt][2] += breg[1][nt].x + mk.x;
            S[nt][3] += breg[1][nt].y + mk.y;
        }

        // ---- warp-local online softmax (quad = 4 lanes share a row) ----
        float alpha[2];
#pragma unroll
        for (int hf = 0; hf < 2; hf++) {
            float mx = S[0][hf * 2];
#pragma unroll
            for (int nt = 0; nt < 8; nt++) {
                mx = fmaxf(mx, S[nt][hf * 2 + 0]);
                mx = fmaxf(mx, S[nt][hf * 2 + 1]);
            }
            mx = fmaxf(mx, __shfl_xor_sync(0xffffffffu, mx, 1));
            mx = fmaxf(mx, __shfl_xor_sync(0xffffffffu, mx, 2));
            float mnew = fmaxf(m_i[hf], mx);
            alpha[hf] = __expf(m_i[hf] - mnew);
            m_i[hf] = mnew;
            float s = 0.0f;
#pragma unroll
            for (int nt = 0; nt < 8; nt++) {
                float e0 = __expf(S[nt][hf * 2 + 0] - mnew);
                float e1 = __expf(S[nt][hf * 2 + 1] - mnew);
                s += e0 + e1;
                // store P back as tf32 bit pattern (for shuffle + mma)
                S[nt][hf * 2 + 0] = __uint_as_float(f2tf(e0));
                S[nt][hf * 2 + 1] = __uint_as_float(f2tf(e1));
            }
            s += __shfl_xor_sync(0xffffffffu, s, 1);
            s += __shfl_xor_sync(0xffffffffu, s, 2);
            l_i[hf] = l_i[hf] * alpha[hf] + s;
        }
        // rescale O
#pragma unroll
        for (int nt = 0; nt < 8; nt++) {
            O[nt][0] *= alpha[0];
            O[nt][1] *= alpha[0];
            O[nt][2] *= alpha[1];
            O[nt][3] *= alpha[1];
        }

        // ---- O += P @ V  (A-frags via intra-warp shuffle from S C-frags) ----
        const int srcA = (lane & 28) | (tig >> 1);
        const int srcB = srcA + 2;
        const bool odd = (tig & 1);
#pragma unroll
        for (int ks = 0; ks < 8; ks++) {
            const int kq = ks << 3;
            float e0A = __shfl_sync(0xffffffffu, S[ks][0], srcA);
            float e1A = __shfl_sync(0xffffffffu, S[ks][1], srcA);
            float e2A = __shfl_sync(0xffffffffu, S[ks][2], srcA);
            float e3A = __shfl_sync(0xffffffffu, S[ks][3], srcA);
            float e0B = __shfl_sync(0xffffffffu, S[ks][0], srcB);
            float e1B = __shfl_sync(0xffffffffu, S[ks][1], srcB);
            float e2B = __shfl_sync(0xffffffffu, S[ks][2], srcB);
            float e3B = __shfl_sync(0xffffffffu, S[ks][3], srcB);
            uint32_t a[4];
            a[0] = __float_as_uint(odd ? e1A : e0A);
            a[1] = __float_as_uint(odd ? e3A : e2A);
            a[2] = __float_as_uint(odd ? e1B : e0B);
            a[3] = __float_as_uint(odd ? e3B : e2B);
#pragma unroll
            for (int nt = 0; nt < 8; nt++) {
                int col = (nt << 3) + gid;
                uint32_t bb[2];
                bb[0] = Vs[(kq + tig) * 72 + col];
                bb[1] = Vs[(kq + tig + 4) * 72 + col];
                mma_tf32(O[nt], a, bb);
            }
        }
    }

    // ---- finalize ----
#pragma unroll
    for (int hf = 0; hf < 2; hf++) {
        int row = qt * 128 + W16 + gid + (hf << 3);
        float inv = 1.0f / l_i[hf];
#pragma unroll
        for (int nt = 0; nt < 8; nt++) {
            int dcol = (nt << 3) + (tig << 1);
            float2 o2;
            o2.x = O[nt][hf * 2 + 0] * inv;
            o2.y = O[nt][hf * 2 + 1] * inv;
            *(float2*)(aout + ((size_t)b * CN + row) * CI + h * 64 + dcol) = o2;
        }
    }
}

// ---------------------------------------------------------------------------
extern "C" void kernel_launch(void* const* d_in, const int* in_sizes, int n_in,
                              void* d_out, int out_size) {
    (void)in_sizes; (void)n_in; (void)out_size;
    const float* x    = (const float*)d_in[0];
    const float* bias = (const float*)d_in[1];
    const int*   mask = (const int*)d_in[2];
    const float* Wq   = (const float*)d_in[3];
    const float* Wkv  = (const float*)d_in[4];
    const float* Wo   = (const float*)d_in[5];
    const float* bo   = (const float*)d_in[6];
    float* out = (float*)d_out;

    float *qp, *kp, *vp, *aop;
    cudaGetSymbolAddress((void**)&qp, g_q);
    cudaGetSymbolAddress((void**)&kp, g_k);
    cudaGetSymbolAddress((void**)&vp, g_v);
    cudaGetSymbolAddress((void**)&aop, g_ao);

    cudaFuncSetAttribute(attn_kernel,
                         cudaFuncAttributeMaxDynamicSharedMemorySize, SMEM_ATT);

    dim3 gg(8, 32), bb(256);
    gemm_tf32<<<gg, bb>>>(x, Wq, nullptr, qp, 1024, 1, ATT_SCALE);
    gemm_tf32<<<gg, bb>>>(x, Wkv, nullptr, kp, 2048, 1, 1.0f);
    gemm_tf32<<<gg, bb>>>(x, Wkv + 1024, nullptr, vp, 2048, 1, 1.0f);
    attn_kernel<<<dim3(16, 16, 2), bb, SMEM_ATT>>>(bias, mask, qp, kp, vp, aop);
    gemm_tf32<<<gg, bb>>>(aop, Wo, bo, out, 1024, 0, 1.0f);
}